// round 5
// baseline (speedup 1.0000x reference)
#include <cuda_runtime.h>
#include <math.h>

// ---------------------------------------------------------------------------
// GCN 2-layer: out = sigmoid( S*( relu( S*X*W0 + b0 ) * W1 ) + b1 )
// with S = D^-1/2 (A + I) D^-1/2.
// Restructured using linearity:  S*(X W) = (S X) W.
//   layer1: agg0 = S*X   (scatter 64 feats)  -> h = relu(agg0*W0 + b0)
//   layer2: hw = h*W1    (GEMM first)        -> out = sigmoid(S*hw + b1)
// ---------------------------------------------------------------------------

#define NN 100000
#define EE 1600000

__device__ int   g_is_i32;
__device__ int   g_deg[NN];
__device__ float g_dis[NN];
__device__ int   g_src[EE];
__device__ int   g_dst[EE];
__device__ float g_norm[EE];
__device__ float g_agg0[(size_t)NN * 64];   // S*X
__device__ float g_h[(size_t)NN * 128];     // relu(agg0*W0+b0)
__device__ float g_hw[(size_t)NN * 64];     // h*W1

// --- dtype detection: jax without x64 silently downcasts int64 -> int32 ----
__global__ void k_detect(const void* ei, int n, int e) {
    __shared__ int bad;
    if (threadIdx.x == 0) bad = 0;
    __syncthreads();
    const long long* p = (const long long*)ei;
    int cnt = e < 2048 ? e : 2048;
    int mybad = 0;
    for (int i = threadIdx.x; i < cnt; i += blockDim.x) {
        long long v = p[i];
        if (v < 0 || v >= (long long)n) mybad = 1;
    }
    if (mybad) atomicOr(&bad, 1);
    __syncthreads();
    if (threadIdx.x == 0) g_is_i32 = bad;  // bad int64 values => data is int32
}

__global__ void k_init_deg(int n) {
    int i = blockIdx.x * blockDim.x + threadIdx.x;
    if (i < n) g_deg[i] = 1;  // self loop
}

__global__ void k_count_deg(const void* ei, int E) {
    int e = blockIdx.x * blockDim.x + threadIdx.x;
    if (e >= E) return;
    int ii = g_is_i32;
    int d = ii ? ((const int*)ei)[E + e] : (int)((const long long*)ei)[E + e];
    atomicAdd(&g_deg[d], 1);
}

__global__ void k_dis(int n) {
    int i = blockIdx.x * blockDim.x + threadIdx.x;
    if (i < n) g_dis[i] = rsqrtf((float)g_deg[i]);
}

__global__ void k_prep(const void* ei, int E) {
    int e = blockIdx.x * blockDim.x + threadIdx.x;
    if (e >= E) return;
    int ii = g_is_i32;
    int s, d;
    if (ii) {
        s = ((const int*)ei)[e];
        d = ((const int*)ei)[E + e];
    } else {
        s = (int)((const long long*)ei)[e];
        d = (int)((const long long*)ei)[E + e];
    }
    g_src[e] = s;
    g_dst[e] = d;
    g_norm[e] = g_dis[s] * g_dis[d];
}

// agg0 = dis^2 * x   (self-loop term), then scatter adds the rest
__global__ void k_self1(const float4* __restrict__ x4, int n16) {
    int g = blockIdx.x * blockDim.x + threadIdx.x;
    if (g >= n16) return;
    int row = g >> 4;
    float d2 = g_dis[row] * g_dis[row];
    float4 v = x4[g];
    ((float4*)g_agg0)[g] = make_float4(v.x * d2, v.y * d2, v.z * d2, v.w * d2);
}

__global__ __launch_bounds__(256) void k_scat1(const float4* __restrict__ x4, int total) {
    int g = blockIdx.x * blockDim.x + threadIdx.x;
    if (g >= total) return;
    int e = g >> 4, f = g & 15;
    int s = g_src[e], d = g_dst[e];
    float nr = g_norm[e];
    float4 v = x4[s * 16 + f];
    float4* p = ((float4*)g_agg0) + (d * 16 + f);
    asm volatile("red.global.add.v4.f32 [%0], {%1,%2,%3,%4};"
                 :: "l"(p), "f"(v.x * nr), "f"(v.y * nr), "f"(v.z * nr), "f"(v.w * nr)
                 : "memory");
}

// h = relu(agg0 * W0 + b0)   [N,64] x [64,128]
__global__ __launch_bounds__(256) void k_gemm1(const float* __restrict__ W,
                                               const float* __restrict__ bias,
                                               int N) {
    __shared__ float As[64][64];    // [k][m]
    __shared__ float Bs[64][128];   // [k][n]
    int t = threadIdx.x;
    int mb = blockIdx.x * 64;
    {
        int rl = t >> 4;
        int kq = (t & 15) * 4;
#pragma unroll
        for (int r = 0; r < 4; r++) {
            int row = rl + r * 16;
            int grow = mb + row;
            float4 v = make_float4(0.f, 0.f, 0.f, 0.f);
            if (grow < N) v = *(const float4*)(g_agg0 + (size_t)grow * 64 + kq);
            As[kq + 0][row] = v.x; As[kq + 1][row] = v.y;
            As[kq + 2][row] = v.z; As[kq + 3][row] = v.w;
        }
    }
    {
        const float4* W4 = (const float4*)W;
#pragma unroll
        for (int i = 0; i < 8; i++) {
            int q = t + i * 256;      // 0..2047
            int k = q >> 5, n4 = q & 31;
            ((float4*)&Bs[k][0])[n4] = W4[q];
        }
    }
    __syncthreads();
    int m0 = (t >> 4) * 4, n0 = (t & 15) * 8;
    float acc[4][8];
#pragma unroll
    for (int i = 0; i < 4; i++)
#pragma unroll
        for (int j = 0; j < 8; j++) acc[i][j] = 0.f;
#pragma unroll 8
    for (int k = 0; k < 64; k++) {
        float4 a = *(const float4*)&As[k][m0];
        float4 bA = *(const float4*)&Bs[k][n0];
        float4 bB = *(const float4*)&Bs[k][n0 + 4];
        float av[4] = {a.x, a.y, a.z, a.w};
        float bv[8] = {bA.x, bA.y, bA.z, bA.w, bB.x, bB.y, bB.z, bB.w};
#pragma unroll
        for (int i = 0; i < 4; i++)
#pragma unroll
            for (int j = 0; j < 8; j++) acc[i][j] += av[i] * bv[j];
    }
    float bb[8];
#pragma unroll
    for (int j = 0; j < 8; j++) bb[j] = bias[n0 + j];
#pragma unroll
    for (int i = 0; i < 4; i++) {
        int grow = mb + m0 + i;
        if (grow < N) {
            float4 o1, o2;
            o1.x = fmaxf(acc[i][0] + bb[0], 0.f);
            o1.y = fmaxf(acc[i][1] + bb[1], 0.f);
            o1.z = fmaxf(acc[i][2] + bb[2], 0.f);
            o1.w = fmaxf(acc[i][3] + bb[3], 0.f);
            o2.x = fmaxf(acc[i][4] + bb[4], 0.f);
            o2.y = fmaxf(acc[i][5] + bb[5], 0.f);
            o2.z = fmaxf(acc[i][6] + bb[6], 0.f);
            o2.w = fmaxf(acc[i][7] + bb[7], 0.f);
            *(float4*)(g_h + (size_t)grow * 128 + n0) = o1;
            *(float4*)(g_h + (size_t)grow * 128 + n0 + 4) = o2;
        }
    }
}

// hw = h * W1   [N,128] x [128,64]  (bias applied after aggregation)
__global__ __launch_bounds__(256) void k_gemm2(const float* __restrict__ W, int N) {
    __shared__ float As[64][64];   // [k][m]
    __shared__ float Bs[64][64];   // [k][n]
    int t = threadIdx.x;
    int mb = blockIdx.x * 64;
    int m0 = (t >> 4) * 4, n0 = (t & 15) * 4;
    float acc[4][4];
#pragma unroll
    for (int i = 0; i < 4; i++)
#pragma unroll
        for (int j = 0; j < 4; j++) acc[i][j] = 0.f;

    for (int kc = 0; kc < 2; kc++) {
        {
            int rl = t >> 4;
            int kq = (t & 15) * 4;
#pragma unroll
            for (int r = 0; r < 4; r++) {
                int row = rl + r * 16;
                int grow = mb + row;
                float4 v = make_float4(0.f, 0.f, 0.f, 0.f);
                if (grow < N) v = *(const float4*)(g_h + (size_t)grow * 128 + kc * 64 + kq);
                As[kq + 0][row] = v.x; As[kq + 1][row] = v.y;
                As[kq + 2][row] = v.z; As[kq + 3][row] = v.w;
            }
        }
        {
            const float4* W4 = (const float4*)(W + kc * 64 * 64);
#pragma unroll
            for (int i = 0; i < 4; i++) {
                int q = t + i * 256;   // 0..1023
                int k = q >> 4, n4 = q & 15;
                ((float4*)&Bs[k][0])[n4] = W4[q];
            }
        }
        __syncthreads();
#pragma unroll 8
        for (int k = 0; k < 64; k++) {
            float4 a = *(const float4*)&As[k][m0];
            float4 b = *(const float4*)&Bs[k][n0];
            float av[4] = {a.x, a.y, a.z, a.w};
            float bv[4] = {b.x, b.y, b.z, b.w};
#pragma unroll
            for (int i = 0; i < 4; i++)
#pragma unroll
                for (int j = 0; j < 4; j++) acc[i][j] += av[i] * bv[j];
        }
        __syncthreads();
    }
#pragma unroll
    for (int i = 0; i < 4; i++) {
        int grow = mb + m0 + i;
        if (grow < N)
            *(float4*)(g_hw + (size_t)grow * 64 + n0) =
                make_float4(acc[i][0], acc[i][1], acc[i][2], acc[i][3]);
    }
}

// out = dis^2 * hw  (self-loop), then scatter adds the rest
__global__ void k_self2(float4* __restrict__ out4, int n16) {
    int g = blockIdx.x * blockDim.x + threadIdx.x;
    if (g >= n16) return;
    int row = g >> 4;
    float d2 = g_dis[row] * g_dis[row];
    float4 v = ((const float4*)g_hw)[g];
    out4[g] = make_float4(v.x * d2, v.y * d2, v.z * d2, v.w * d2);
}

__global__ __launch_bounds__(256) void k_scat2(float4* __restrict__ out4, int total) {
    int g = blockIdx.x * blockDim.x + threadIdx.x;
    if (g >= total) return;
    int e = g >> 4, f = g & 15;
    int s = g_src[e], d = g_dst[e];
    float nr = g_norm[e];
    float4 v = ((const float4*)g_hw)[s * 16 + f];
    float4* p = out4 + (d * 16 + f);
    asm volatile("red.global.add.v4.f32 [%0], {%1,%2,%3,%4};"
                 :: "l"(p), "f"(v.x * nr), "f"(v.y * nr), "f"(v.z * nr), "f"(v.w * nr)
                 : "memory");
}

__global__ void k_fin(float4* __restrict__ out4, const float4* __restrict__ b1, int n16) {
    int g = blockIdx.x * blockDim.x + threadIdx.x;
    if (g >= n16) return;
    float4 v = out4[g];
    float4 bb = b1[g & 15];
    v.x = 1.f / (1.f + __expf(-(v.x + bb.x)));
    v.y = 1.f / (1.f + __expf(-(v.y + bb.y)));
    v.z = 1.f / (1.f + __expf(-(v.z + bb.z)));
    v.w = 1.f / (1.f + __expf(-(v.w + bb.w)));
    out4[g] = v;
}

extern "C" void kernel_launch(void* const* d_in, const int* in_sizes, int n_in,
                              void* d_out, int out_size) {
    const float* x  = (const float*)d_in[0];
    const void*  ei = d_in[1];
    const float* W0 = (const float*)d_in[2];
    const float* b0 = (const float*)d_in[3];
    const float* W1 = (const float*)d_in[4];
    const float* b1 = (const float*)d_in[5];
    float* out = (float*)d_out;

    int N = in_sizes[0] / 64;       // 100000
    int E = in_sizes[1] / 2;        // 1600000 (element count same for i32/i64)
    int n16 = N * 16;               // float4 count of [N,64]
    int e16 = E * 16;

    const int T = 256;
    k_detect<<<1, T>>>(ei, N, E);
    k_init_deg<<<(N + T - 1) / T, T>>>(N);
    k_count_deg<<<(E + T - 1) / T, T>>>(ei, E);
    k_dis<<<(N + T - 1) / T, T>>>(N);
    k_prep<<<(E + T - 1) / T, T>>>(ei, E);

    k_self1<<<(n16 + T - 1) / T, T>>>((const float4*)x, n16);
    k_scat1<<<(e16 + T - 1) / T, T>>>((const float4*)x, e16);
    k_gemm1<<<(N + 63) / 64, 256>>>(W0, b0, N);
    k_gemm2<<<(N + 63) / 64, 256>>>(W1, N);
    k_self2<<<(n16 + T - 1) / T, T>>>((float4*)out, n16);
    k_scat2<<<(e16 + T - 1) / T, T>>>((float4*)out, e16);
    k_fin<<<(n16 + T - 1) / T, T>>>((float4*)out, (const float4*)b1, n16);
}